// round 2
// baseline (speedup 1.0000x reference)
#include <cuda_runtime.h>
#include <cuda_bf16.h>
#include <cstdint>

// Problem constants (fixed by reference: B=2048, C=1024, E=16384)
#define BB 2048
#define CC 1024
#define EE 16384
#define TB 16          // batch rows per CTA tile
#define ESPLIT 4       // e-dimension split across grid.y
#define ECHUNK (EE / ESPLIT)   // 4096 pairs per CTA
#define THREADS 512
#define ROWF2 17       // padded row stride in float2 (16 + 1 pad)

// total = 0.01/(B*C) * sum_{b,e} s_l*(1-s_r)*(1 - t_l + t_r)
#define SCALE (0.01f / (2048.0f * 1024.0f))

// Scratch: precomputed (sigmoid(input), target) pairs, [B*C] float2 = 16 MB.
__device__ float2 g_st[BB * CC];

// ---------------------------------------------------------------------------
// Kernel A: precompute sigmoid + pack with target; also zero the output scalar.
// ---------------------------------------------------------------------------
__global__ void prep_kernel(const float* __restrict__ input,
                            const float* __restrict__ target,
                            float* __restrict__ out) {
    int i = blockIdx.x * blockDim.x + threadIdx.x;
    if (i == 0) out[0] = 0.0f;
    if (i < BB * CC) {
        float x = input[i];
        float s = __fdividef(1.0f, 1.0f + __expf(-x));
        g_st[i] = make_float2(s, target[i]);
    }
}

// ---------------------------------------------------------------------------
// Kernel B: main reduction.
// Grid: (B/TB, ESPLIT). Block: 512 threads.
// smem: ST[CC][ROWF2] float2 (139264 B) + filters int2[ECHUNK] (32768 B)
//       + 16 floats reduction scratch.
// Warp layout: lanes 0..15 handle pair e0 across 16 b's; lanes 16..31 handle e1.
// Gather loads are 16 consecutive float2 -> conflict-free LDS.64.
// ---------------------------------------------------------------------------
extern __shared__ unsigned char dyn_smem[];

__global__ void __launch_bounds__(THREADS, 1)
main_kernel(const int* __restrict__ filter_l,
            const int* __restrict__ filter_r,
            float* __restrict__ out) {
    float2* st = reinterpret_cast<float2*>(dyn_smem);                 // CC*ROWF2 float2
    int2*  smf = reinterpret_cast<int2*>(dyn_smem + CC * ROWF2 * sizeof(float2)); // ECHUNK
    float* red = reinterpret_cast<float*>(dyn_smem + CC * ROWF2 * sizeof(float2)
                                                  + ECHUNK * sizeof(int2));       // 16

    const int tid  = threadIdx.x;
    const int lane = tid & 31;
    const int warp = tid >> 5;
    const int j    = lane & 15;       // batch index within tile
    const int sub  = lane >> 4;       // which of 2 pairs this half-warp handles

    const int b0 = blockIdx.x * TB;
    const int ebase = blockIdx.y * ECHUNK;

    // Stage (s,t) tile into smem, transposed: st[c*ROWF2 + j] = g_st[(b0+j)*CC + c]
    // Consecutive threads -> consecutive c: coalesced LDG.64; STS conflict deg ~2.
    for (int idx = tid; idx < TB * CC; idx += THREADS) {
        int cc = idx & (CC - 1);
        int jj = idx >> 10;           // CC == 1024
        st[cc * ROWF2 + jj] = g_st[(b0 + jj) * CC + cc];
    }

    // Stage this CTA's filter pair chunk.
    for (int idx = tid; idx < ECHUNK; idx += THREADS) {
        smf[idx] = make_int2(filter_l[ebase + idx], filter_r[ebase + idx]);
    }

    __syncthreads();

    // Main loop: each iteration a warp consumes 4 pairs x 16 batch rows = 64 terms.
    const float2* myst = st + j;
    float acc0 = 0.0f, acc1 = 0.0f;

    const int base = (warp << 1) + sub;      // 0..31
    #pragma unroll 4
    for (int it = 0; it < ECHUNK / 32; it += 2) {
        int2 f0 = smf[it * 32 + base];
        int2 f1 = smf[(it + 1) * 32 + base];

        float2 L0 = myst[f0.x * ROWF2];
        float2 R0 = myst[f0.y * ROWF2];
        float2 L1 = myst[f1.x * ROWF2];
        float2 R1 = myst[f1.y * ROWF2];

        // term = s_l*(1-s_r) * (1 - t_l + t_r)
        float m0 = fmaf(-L0.x, R0.x, L0.x);
        float w0 = (R0.y - L0.y) + 1.0f;
        acc0 = fmaf(m0, w0, acc0);

        float m1 = fmaf(-L1.x, R1.x, L1.x);
        float w1 = (R1.y - L1.y) + 1.0f;
        acc1 = fmaf(m1, w1, acc1);
    }
    float acc = acc0 + acc1;

    // Warp butterfly reduce.
    #pragma unroll
    for (int off = 16; off > 0; off >>= 1)
        acc += __shfl_xor_sync(0xFFFFFFFFu, acc, off);

    if (lane == 0) red[warp] = acc;
    __syncthreads();

    if (warp == 0) {
        float v = (lane < THREADS / 32) ? red[lane] : 0.0f;
        #pragma unroll
        for (int off = 8; off > 0; off >>= 1)
            v += __shfl_xor_sync(0xFFFFFFFFu, v, off);
        if (lane == 0)
            atomicAdd(out, v * SCALE);
    }
}

// ---------------------------------------------------------------------------
extern "C" void kernel_launch(void* const* d_in, const int* in_sizes, int n_in,
                              void* d_out, int out_size) {
    const float* input    = (const float*)d_in[0];
    const float* target   = (const float*)d_in[1];
    const int*   filter_l = (const int*)d_in[2];
    const int*   filter_r = (const int*)d_in[3];
    float* out = (float*)d_out;

    (void)in_sizes; (void)n_in; (void)out_size;

    const int smem_bytes = CC * ROWF2 * (int)sizeof(float2)
                         + ECHUNK * (int)sizeof(int2)
                         + 16 * (int)sizeof(float);   // 172,096 B

    cudaFuncSetAttribute(main_kernel,
                         cudaFuncAttributeMaxDynamicSharedMemorySize,
                         smem_bytes);

    prep_kernel<<<(BB * CC + 255) / 256, 256>>>(input, target, out);

    dim3 grid(BB / TB, ESPLIT);
    main_kernel<<<grid, THREADS, smem_bytes>>>(filter_l, filter_r, out);
}

// round 3
// speedup vs baseline: 1.3772x; 1.3772x over previous
#include <cuda_runtime.h>
#include <cuda_fp16.h>
#include <cstdint>

// Problem constants (fixed by reference: B=2048, C=1024, E=16384)
#define BB 2048
#define CC 1024
#define EE 16384
#define TB 32                  // batch rows per tile (== warp width)
#define NBT (BB / TB)          // 64 btiles
#define ESPLIT 6
#define ECH 2732               // ceil(EE/ESPLIT) rounded to even
#define THREADS 512
#define WARPS (THREADS / 32)

// total = 0.01/(B*C) * sum_{b,e} s_l*(1-s_r)*(1 - t_l + t_r)
#define SCALE (0.01f / (2048.0f * 1024.0f))

// Pre-transposed, sign-encoded activations: x = (t ? -s : +s) as fp16.
// Layout: g_xt[bt*CC*TB + c*TB + j], j = b within tile. 4 MB (L2-resident).
__device__ __half g_xt[BB * CC];
// Zipped filter pairs.
__device__ int2 g_f[EE];

// ---------------------------------------------------------------------------
// Prep A: sigmoid + sign-encode + transpose into g_xt.
// Grid (NBT, CC/64), 256 threads. Tile: 32 b x 64 c.
// ---------------------------------------------------------------------------
__global__ void prep_tr(const float* __restrict__ input,
                        const float* __restrict__ target) {
    __shared__ __half sm[64 * 33];   // [c_local][b] padded
    const int bt = blockIdx.x;
    const int c0 = blockIdx.y * 64;
    const int tid = threadIdx.x;

    // Load coalesced over c, compute x.
    for (int idx = tid; idx < 64 * 32; idx += 256) {
        int cl = idx & 63;
        int bl = idx >> 6;
        int g = (bt * TB + bl) * CC + c0 + cl;
        float s = __fdividef(1.0f, 1.0f + __expf(-input[g]));
        float x = (target[g] > 0.5f) ? -s : s;
        sm[cl * 33 + bl] = __float2half(x);
    }
    __syncthreads();

    // Write coalesced over b (32 fp16 = 64B per c-row).
    for (int idx = tid; idx < 64 * 32; idx += 256) {
        int cl = idx >> 5;
        int bl = idx & 31;
        g_xt[(bt * CC + c0 + cl) * TB + bl] = sm[cl * 33 + bl];
    }
}

// ---------------------------------------------------------------------------
// Prep B: zip filters + zero output scalar.
// ---------------------------------------------------------------------------
__global__ void prep_misc(const int* __restrict__ filter_l,
                          const int* __restrict__ filter_r,
                          float* __restrict__ out) {
    int i = blockIdx.x * blockDim.x + threadIdx.x;
    if (i == 0) out[0] = 0.0f;
    if (i < EE) g_f[i] = make_int2(filter_l[i], filter_r[i]);
}

// ---------------------------------------------------------------------------
// Main reduction. Grid (NBT, ESPLIT) = 384 CTAs, 512 threads, 3 CTAs/SM.
// smem = 64KB tile + 16 floats. Warp handles pair e for all 32 batch rows:
// gather = 32 consecutive fp16 (64B, conflict-free).
// term = max(xl,0)*(1-|xr|) + |xl|*(xr<0 ? 1+xr : 0)
// ---------------------------------------------------------------------------
extern __shared__ unsigned char dyn_smem[];

__global__ void __launch_bounds__(THREADS, 3)
main_kernel(float* __restrict__ out) {
    __half* st = reinterpret_cast<__half*>(dyn_smem);               // CC*TB fp16
    float* red = reinterpret_cast<float*>(dyn_smem + CC * TB * 2);  // WARPS

    const int tid  = threadIdx.x;
    const int lane = tid & 31;
    const int warp = tid >> 5;
    const int bt = blockIdx.x;

    // Stage tile: contiguous 64KB copy, vectorized.
    {
        const int4* src = reinterpret_cast<const int4*>(g_xt + bt * CC * TB);
        int4* dst = reinterpret_cast<int4*>(st);
        #pragma unroll
        for (int i = 0; i < (CC * TB * 2) / 16 / THREADS; i++)
            dst[tid + i * THREADS] = src[tid + i * THREADS];
    }
    __syncthreads();

    const int ebase = blockIdx.y * ECH;
    const int eend  = min(EE, ebase + ECH);

    const __half* stl = st + lane;
    float a0 = 0.0f, a1 = 0.0f, b0 = 0.0f, b1 = 0.0f;

    // Warp-cyclic over pair indices, 2 pairs per step via one LDG.128.
    #pragma unroll 2
    for (int e0 = ebase + warp * 2; e0 < eend; e0 += WARPS * 2) {
        int4 f = *reinterpret_cast<const int4*>(g_f + e0);  // (l0,r0,l1,r1)

        float xl0 = __half2float(stl[f.x * TB]);
        float xr0 = __half2float(stl[f.y * TB]);
        float xl1 = __half2float(stl[f.z * TB]);
        float xr1 = __half2float(stl[f.w * TB]);

        float u0 = fmaxf(xl0, 0.0f);
        float om0 = 1.0f - fabsf(xr0);
        a0 = fmaf(u0, om0, a0);
        float v0 = (xr0 < 0.0f) ? (1.0f + xr0) : 0.0f;
        a1 = fmaf(fabsf(xl0), v0, a1);

        float u1 = fmaxf(xl1, 0.0f);
        float om1 = 1.0f - fabsf(xr1);
        b0 = fmaf(u1, om1, b0);
        float v1 = (xr1 < 0.0f) ? (1.0f + xr1) : 0.0f;
        b1 = fmaf(fabsf(xl1), v1, b1);
    }
    float acc = (a0 + a1) + (b0 + b1);

    #pragma unroll
    for (int off = 16; off > 0; off >>= 1)
        acc += __shfl_xor_sync(0xFFFFFFFFu, acc, off);

    if (lane == 0) red[warp] = acc;
    __syncthreads();

    if (warp == 0) {
        float v = (lane < WARPS) ? red[lane] : 0.0f;
        #pragma unroll
        for (int off = 8; off > 0; off >>= 1)
            v += __shfl_xor_sync(0xFFFFFFFFu, v, off);
        if (lane == 0)
            atomicAdd(out, v * SCALE);
    }
}

// ---------------------------------------------------------------------------
extern "C" void kernel_launch(void* const* d_in, const int* in_sizes, int n_in,
                              void* d_out, int out_size) {
    const float* input    = (const float*)d_in[0];
    const float* target   = (const float*)d_in[1];
    const int*   filter_l = (const int*)d_in[2];
    const int*   filter_r = (const int*)d_in[3];
    float* out = (float*)d_out;

    (void)in_sizes; (void)n_in; (void)out_size;

    const int smem_bytes = CC * TB * 2 + WARPS * (int)sizeof(float);  // 65,600

    cudaFuncSetAttribute(main_kernel,
                         cudaFuncAttributeMaxDynamicSharedMemorySize,
                         smem_bytes);

    prep_tr<<<dim3(NBT, CC / 64), 256>>>(input, target);
    prep_misc<<<(EE + 255) / 256, 256>>>(filter_l, filter_r, out);

    main_kernel<<<dim3(NBT, ESPLIT), THREADS, smem_bytes>>>(out);
}

// round 4
// speedup vs baseline: 1.8563x; 1.3478x over previous
#include <cuda_runtime.h>
#include <cuda_fp16.h>
#include <cstdint>

// Problem constants (fixed by reference: B=2048, C=1024, E=16384)
#define BB 2048
#define CC 1024
#define EE 16384
#define NP 32                  // number of 64-row btile-pairs (BB/64)
#define ESPLIT 13
#define ECH 1264               // pairs per CTA chunk (even); 13*1264 >= 16384
#define THREADS 512
#define WARPS (THREADS / 32)

// total = 0.01/(B*C) * sum_{b,e} s_l*(1-s_r)*(1 - t_l + t_r)
#define SCALE (0.01f / (2048.0f * 1024.0f))

// Sign-encoded activations x = (1-2t)*sigmoid(in), fp16, pair-interleaved:
// g_xt2[p*CC*32 + c*32 + j] = half2( x[b=64p+j][c], x[b=64p+32+j][c] ). 4 MB.
__device__ __half2 g_xt2[NP * CC * 32];

// ---------------------------------------------------------------------------
// Prep: sigmoid via tanh (1 MUFU), sign-encode, transpose+interleave.
// Grid (NP, CC/64), 256 threads. Tile: 64 b x 64 c.
// ---------------------------------------------------------------------------
__global__ void prep_tr(const float* __restrict__ input,
                        const float* __restrict__ target,
                        float* __restrict__ out) {
    __shared__ __half sm[64 * 65];   // [c_local][b_local] padded
    const int p  = blockIdx.x;
    const int c0 = blockIdx.y * 64;
    const int tid = threadIdx.x;

    if (p == 0 && blockIdx.y == 0 && tid == 0) out[0] = 0.0f;

    // Load coalesced over c; x = cse + cse*tanh(in*0.5), cse = 0.5-t (= +-0.5).
    #pragma unroll
    for (int k = 0; k < 16; k++) {
        int idx = tid + k * 256;
        int cl = idx & 63;
        int bl = idx >> 6;
        int g = (p * 64 + bl) * CC + c0 + cl;
        float th;
        asm("tanh.approx.f32 %0, %1;" : "=f"(th) : "f"(input[g] * 0.5f));
        float cse = 0.5f - target[g];
        sm[cl * 65 + bl] = __float2half(fmaf(cse, th, cse));
    }
    __syncthreads();

    // Write coalesced over j: 32 half2 = 128B per c row.
    #pragma unroll
    for (int k = 0; k < 8; k++) {
        int idx = tid + k * 256;
        int cl = idx >> 5;
        int j  = idx & 31;
        g_xt2[(p * CC + c0 + cl) * 32 + j] =
            __halves2half2(sm[cl * 65 + j], sm[cl * 65 + 32 + j]);
    }
}

// ---------------------------------------------------------------------------
// Main reduction. Grid (NP, ESPLIT) = 416 CTAs (single wave @ 3 CTAs/SM).
// smem = 64KB tile (CC x 32 half2) + WARPS floats.
// Warp handles pair e for 64 batch rows: one LDS.32 (half2) per operand,
// 32 consecutive 4B words -> conflict-free.
// term2 = (1-|xr|) * (max(xl,0) + |xl|*[xr<0])   (packed fp16x2)
// ---------------------------------------------------------------------------
extern __shared__ unsigned char dyn_smem[];

__global__ void __launch_bounds__(THREADS, 3)
main_kernel(const int* __restrict__ filter_l,
            const int* __restrict__ filter_r,
            float* __restrict__ out) {
    __half2* st = reinterpret_cast<__half2*>(dyn_smem);                 // CC*32
    float* red = reinterpret_cast<float*>(dyn_smem + CC * 32 * 4);      // WARPS

    const int tid  = threadIdx.x;
    const int lane = tid & 31;
    const int warp = tid >> 5;
    const int p = blockIdx.x;

    // Stage tile: contiguous 64KB copy.
    {
        const int4* src = reinterpret_cast<const int4*>(g_xt2 + p * CC * 32);
        int4* dst = reinterpret_cast<int4*>(st);
        #pragma unroll
        for (int i = 0; i < (CC * 32 * 4) / 16 / THREADS; i++)
            dst[tid + i * THREADS] = src[tid + i * THREADS];
    }
    __syncthreads();

    const int ebase = blockIdx.y * ECH;
    const int eend  = min(EE, ebase + ECH);

    const __half2* stl = st + lane;
    const __half2 zero2 = __float2half2_rn(0.0f);
    const __half2 one2  = __float2half2_rn(1.0f);

    float facc = 0.0f;
    __half2 hacc = zero2;
    int cnt = 0;

    // 2 pairs per step; half2 partials drained to f32 every 8 pairs.
    #pragma unroll 4
    for (int e = ebase + warp * 2; e < eend; e += WARPS * 2) {
        int2 fl = *reinterpret_cast<const int2*>(filter_l + e);
        int2 fr = *reinterpret_cast<const int2*>(filter_r + e);

        __half2 xl0 = stl[fl.x * 32];
        __half2 xr0 = stl[fr.x * 32];
        __half2 xl1 = stl[fl.y * 32];
        __half2 xr1 = stl[fr.y * 32];

        __half2 om0 = __hsub2(one2, __habs2(xr0));
        __half2 w0  = __hfma2(__habs2(xl0), __hlt2(xr0, zero2),
                              __hmax2(xl0, zero2));
        hacc = __hfma2(om0, w0, hacc);

        __half2 om1 = __hsub2(one2, __habs2(xr1));
        __half2 w1  = __hfma2(__habs2(xl1), __hlt2(xr1, zero2),
                              __hmax2(xl1, zero2));
        hacc = __hfma2(om1, w1, hacc);

        if (++cnt == 4) {
            float2 f2 = __half22float2(hacc);
            facc += f2.x + f2.y;
            hacc = zero2;
            cnt = 0;
        }
    }
    {
        float2 f2 = __half22float2(hacc);
        facc += f2.x + f2.y;
    }

    #pragma unroll
    for (int off = 16; off > 0; off >>= 1)
        facc += __shfl_xor_sync(0xFFFFFFFFu, facc, off);

    if (lane == 0) red[warp] = facc;
    __syncthreads();

    if (warp == 0) {
        float v = (lane < WARPS) ? red[lane] : 0.0f;
        #pragma unroll
        for (int off = 8; off > 0; off >>= 1)
            v += __shfl_xor_sync(0xFFFFFFFFu, v, off);
        if (lane == 0)
            atomicAdd(out, v * SCALE);
    }
}

// ---------------------------------------------------------------------------
extern "C" void kernel_launch(void* const* d_in, const int* in_sizes, int n_in,
                              void* d_out, int out_size) {
    const float* input    = (const float*)d_in[0];
    const float* target   = (const float*)d_in[1];
    const int*   filter_l = (const int*)d_in[2];
    const int*   filter_r = (const int*)d_in[3];
    float* out = (float*)d_out;

    (void)in_sizes; (void)n_in; (void)out_size;

    const int smem_bytes = CC * 32 * 4 + WARPS * (int)sizeof(float);  // 65,600

    cudaFuncSetAttribute(main_kernel,
                         cudaFuncAttributeMaxDynamicSharedMemorySize,
                         smem_bytes);

    prep_tr<<<dim3(NP, CC / 64), 256>>>(input, target, out);
    main_kernel<<<dim3(NP, ESPLIT), THREADS, smem_bytes>>>(filter_l, filter_r, out);
}